// round 8
// baseline (speedup 1.0000x reference)
#include <cuda_runtime.h>
#include <cuda_bf16.h>
#include <math.h>
#include <stdint.h>

#define DD   8
#define FF   1024
#define HH   1024
#define CC   22
#define INN  4096
#define NROW 4096
#define G4   4096
#define NCAT (G4 + FF)    // 5120

typedef __nv_bfloat16 bf16;

// ---------------- arena ----------------
constexpr size_t SZ_X  = (size_t)NROW * INN * 2;
constexpr size_t SZ_W4 = (size_t)G4 * FF * 2;
constexpr size_t SZ_W1 = (size_t)FF * HH * 2;
constexpr size_t SZ_WC = (size_t)NCAT * HH * 2;

constexpr size_t O_XH  = 0;
constexpr size_t O_XL  = O_XH + SZ_X;
constexpr size_t O_WFH = O_XL + SZ_X;
constexpr size_t O_WFL = O_WFH + SZ_W4;
constexpr size_t O_DIH = O_WFL + SZ_W4;
constexpr size_t O_DIL = O_DIH + SZ_W4;
constexpr size_t O_EIH = O_DIL + SZ_W4;
constexpr size_t O_EIL = O_EIH + SZ_W4;
constexpr size_t O_EHH = O_EIL + SZ_W4;
constexpr size_t O_EHL = O_EHH + SZ_W4;
constexpr size_t O_WTH = O_EHL + SZ_W4;
constexpr size_t O_WTL = O_WTH + SZ_W1;
constexpr size_t O_WCH = O_WTL + SZ_W1;      // [NCAT, HH]: rows 0..4095 Wcomb, 4096.. Wdc
constexpr size_t O_WCL = O_WCH + SZ_WC;
constexpr size_t O_FH  = O_WCL + SZ_WC;
constexpr size_t O_FL  = O_FH + SZ_W4;
constexpr size_t O_HH  = O_FL + SZ_W4;
constexpr size_t O_HL  = O_HH + SZ_W4;
constexpr size_t O_LH  = O_HL + SZ_W4;
constexpr size_t O_LL  = O_LH + SZ_W4;
constexpr size_t O_C   = O_LL + SZ_W4;
constexpr size_t O_G   = O_C  + (size_t)NROW * HH * 4;
constexpr size_t O_HF  = O_G  + (size_t)NROW * G4 * 4;
constexpr size_t O_B0  = O_HF + (size_t)NROW * HH * 4;
constexpr size_t O_B1  = O_B0 + (size_t)G4 * 4;     // bcat: 5120 floats
constexpr size_t O_B2  = O_B1 + (size_t)NCAT * 4;
constexpr size_t ARENA = O_B2 + (size_t)G4 * 4;

__device__ __align__(1024) unsigned char g_arena[ARENA];

// ---------------- helpers ----------------
__device__ __forceinline__ uint32_t smem_u32(const void* p) {
    uint32_t a;
    asm("{ .reg .u64 t; cvta.to.shared.u64 t, %1; cvt.u32.u64 %0, t; }" : "=r"(a) : "l"(p));
    return a;
}
__device__ __forceinline__ void ldsm4(uint32_t& r0, uint32_t& r1, uint32_t& r2, uint32_t& r3,
                                      uint32_t addr) {
    asm volatile("ldmatrix.sync.aligned.m8n8.x4.shared.b16 {%0,%1,%2,%3}, [%4];"
                 : "=r"(r0), "=r"(r1), "=r"(r2), "=r"(r3) : "r"(addr));
}
__device__ __forceinline__ void mma16816(float* c, const uint32_t* a, const uint32_t* b) {
    asm volatile("mma.sync.aligned.m16n8k16.row.col.f32.bf16.bf16.f32 "
                 "{%0,%1,%2,%3}, {%4,%5,%6,%7}, {%8,%9}, {%0,%1,%2,%3};"
                 : "+f"(c[0]), "+f"(c[1]), "+f"(c[2]), "+f"(c[3])
                 : "r"(a[0]), "r"(a[1]), "r"(a[2]), "r"(a[3]), "r"(b[0]), "r"(b[1]));
}
__device__ __forceinline__ void split2(float v, unsigned short& hi, unsigned short& lo) {
    bf16 h = __float2bfloat16(v);
    bf16 l = __float2bfloat16(v - __bfloat162float(h));
    hi = *(unsigned short*)&h;
    lo = *(unsigned short*)&l;
}

// ---------------- HMMA split-bf16 GEMM (CTA 256x128, warp 64x64) ----------------
// C[M,N] = sum_p A_p @ B_p^T ; A_p [M,Kp], B_p [N,Kp] row-major bf16.
// Epilogue: cols < N1 -> C1 (+bias, +Cadd, relu, optional split-bf16 out);
//           cols >= N1 -> C2 (+bias only).
struct Passes { const bf16* A[6]; const bf16* B[6]; };

#define STAGES      4
#define ROWPITCH    80
#define A_BYTES     (256 * ROWPITCH)     // 20480
#define B_BYTES     (128 * ROWPITCH)     // 10240
#define STAGE_BYTES (A_BYTES + B_BYTES)  // 30720
#define SMEM_DYN    (STAGES * STAGE_BYTES)

__global__ __launch_bounds__(256, 1)
void tcgemm(Passes P, int nPass, int Kp, int N1,
            const float* __restrict__ bias,
            const float* __restrict__ Cadd, int ldadd,
            float* __restrict__ C1, int ldc1,
            float* __restrict__ C2, int ldc2,
            bf16* __restrict__ Oh, bf16* __restrict__ Ol, int ldo,
            float oscale, int relu)
{
    extern __shared__ __align__(16) unsigned char dsm[];
    const uint32_t sbase = smem_u32(dsm);

    const int tid = threadIdx.x, wid = tid >> 5, lane = tid & 31;
    const int wm = wid >> 1;        // 0..3  (64-row quarters of 256)
    const int wn = wid & 1;         // 0..1  (64-col halves of 128)
    const int tm = blockIdx.y, tn = blockIdx.x;

    const int ck  = Kp >> 5;
    const int nkt = nPass * ck;

    auto load_chunk = [&](int f) {
        const int buf = f & 3;
        const int p = f / ck, ko = (f - p * ck) << 5;
        const bf16* Ag = P.A[p] + (size_t)(tm * 256) * Kp + ko;
        const bf16* Bg = P.B[p] + (size_t)(tn * 128) * Kp + ko;
        const uint32_t sA = sbase + (uint32_t)buf * STAGE_BYTES;
        const uint32_t sB = sA + A_BYTES;
#pragma unroll
        for (int j = 0; j < 4; j++) {                 // A: 256 rows x 4 chunks16
            const int i = tid + 256 * j;
            const int row = i >> 2, ch = i & 3;
            asm volatile("cp.async.cg.shared.global [%0], [%1], 16;"
                         :: "r"(sA + (uint32_t)row * ROWPITCH + (uint32_t)ch * 16),
                            "l"(Ag + (size_t)row * Kp + ch * 8) : "memory");
        }
#pragma unroll
        for (int j = 0; j < 2; j++) {                 // B: 128 rows
            const int i = tid + 256 * j;
            const int row = i >> 2, ch = i & 3;
            asm volatile("cp.async.cg.shared.global [%0], [%1], 16;"
                         :: "r"(sB + (uint32_t)row * ROWPITCH + (uint32_t)ch * 16),
                            "l"(Bg + (size_t)row * Kp + ch * 8) : "memory");
        }
        asm volatile("cp.async.commit_group;" ::: "memory");
    };

    float c[4][8][4];
#pragma unroll
    for (int i = 0; i < 4; i++)
#pragma unroll
        for (int j = 0; j < 8; j++)
#pragma unroll
            for (int k = 0; k < 4; k++) c[i][j][k] = 0.f;

    const uint32_t a_row = (uint32_t)(wm * 64 + (lane & 15));
    const uint32_t a_ch  = (uint32_t)((lane >> 4) * 16);
    const uint32_t b_row = (uint32_t)(wn * 64 + ((lane >> 4) << 3) + (lane & 7));
    const uint32_t b_ch  = (uint32_t)(((lane >> 3) & 1) * 16);

    for (int f = 0; f < STAGES - 1 && f < nkt; f++) load_chunk(f);

    for (int kt = 0; kt < nkt; kt++) {
        int w = nkt - kt - 1;
        if (w > STAGES - 2) w = STAGES - 2;
        if (w == 2)      asm volatile("cp.async.wait_group 2;" ::: "memory");
        else if (w == 1) asm volatile("cp.async.wait_group 1;" ::: "memory");
        else             asm volatile("cp.async.wait_group 0;" ::: "memory");
        __syncthreads();

        const int f = kt + STAGES - 1;
        if (f < nkt) load_chunk(f);

        const uint32_t sA = sbase + (uint32_t)(kt & 3) * STAGE_BYTES;
        const uint32_t sB = sA + A_BYTES;
#pragma unroll
        for (int ks = 0; ks < 2; ks++) {
            uint32_t a[4][4], b[8][2];
#pragma unroll
            for (int mf = 0; mf < 4; mf++) {
                const uint32_t addr = sA + (a_row + mf * 16) * ROWPITCH + ks * 32 + a_ch;
                ldsm4(a[mf][0], a[mf][1], a[mf][2], a[mf][3], addr);
            }
#pragma unroll
            for (int np = 0; np < 4; np++) {
                const uint32_t addr = sB + (b_row + np * 16) * ROWPITCH + ks * 32 + b_ch;
                ldsm4(b[2 * np][0], b[2 * np][1], b[2 * np + 1][0], b[2 * np + 1][1], addr);
            }
#pragma unroll
            for (int mf = 0; mf < 4; mf++)
#pragma unroll
                for (int nf = 0; nf < 8; nf++)
                    mma16816(c[mf][nf], a[mf], b[nf]);
        }
    }

    // ---------------- epilogue ----------------
    const int tr = lane >> 2, tc = (lane & 3) * 2;
#pragma unroll
    for (int mf = 0; mf < 4; mf++) {
#pragma unroll
        for (int half = 0; half < 2; half++) {
            const size_t row = (size_t)tm * 256 + wm * 64 + mf * 16 + tr + half * 8;
            float* c1row = C1 ? C1 + row * (size_t)ldc1 : (float*)0;
            float* c2row = C2 ? C2 + row * (size_t)ldc2 : (float*)0;
            const float* arow = Cadd ? Cadd + row * (size_t)ldadd : (const float*)0;
            bf16* ohr = Oh ? Oh + row * (size_t)ldo : (bf16*)0;
            bf16* olr = Ol ? Ol + row * (size_t)ldo : (bf16*)0;
#pragma unroll
            for (int nf = 0; nf < 8; nf++) {
                const int col = tn * 128 + wn * 64 + nf * 8 + tc;
                float vx = c[mf][nf][half * 2 + 0];
                float vy = c[mf][nf][half * 2 + 1];
                if (bias) { vx += bias[col]; vy += bias[col + 1]; }
                if (col < N1) {
                    if (arow) { vx += arow[col]; vy += arow[col + 1]; }
                    if (relu) { vx = fmaxf(vx, 0.f); vy = fmaxf(vy, 0.f); }
                    if (c1row) *(float2*)(c1row + col) = make_float2(vx, vy);
                    if (ohr) {
                        unsigned short h0, l0, h1, l1;
                        split2(vx * oscale, h0, l0);
                        split2(vy * oscale, h1, l1);
                        *(ushort2*)((unsigned short*)ohr + col) = make_ushort2(h0, h1);
                        *(ushort2*)((unsigned short*)olr + col) = make_ushort2(l0, l1);
                    }
                } else {
                    *(float2*)(c2row + (col - N1)) = make_float2(vx, vy);
                }
            }
        }
    }
}

// ---------------- split fp32 -> (bf16 hi, bf16 lo) ----------------
__global__ void split_kernel(const float* __restrict__ s,
                             bf16* __restrict__ h, bf16* __restrict__ l)
{
    const size_t i = (size_t)blockIdx.x * 256 + threadIdx.x;
    const float4 v = ((const float4*)s)[i];
    unsigned short h0, l0, h1, l1, h2, l2, h3, l3;
    split2(v.x, h0, l0); split2(v.y, h1, l1); split2(v.z, h2, l2); split2(v.w, h3, l3);
    ((ushort4*)h)[i] = make_ushort4(h0, h1, h2, h3);
    ((ushort4*)l)[i] = make_ushort4(l0, l1, l2, l3);
}

// transpose + split: WdcT[h,f] = Wdc[f,h]
__global__ void tsplit_kernel(const float* __restrict__ W,
                              bf16* __restrict__ th, bf16* __restrict__ tl)
{
    __shared__ float t[32][33];
    const int f0 = blockIdx.y * 32, h0 = blockIdx.x * 32;
    t[threadIdx.y][threadIdx.x] = W[(size_t)(f0 + threadIdx.y) * HH + h0 + threadIdx.x];
    __syncthreads();
    const float v = t[threadIdx.x][threadIdx.y];
    unsigned short hi, lo;
    split2(v, hi, lo);
    const size_t o = (size_t)(h0 + threadIdx.y) * FF + f0 + threadIdx.x;
    ((unsigned short*)th)[o] = hi;
    ((unsigned short*)tl)[o] = lo;
}

// ---------------- LSTM pointwise ----------------
__device__ __forceinline__ float sigm(float x) { return 1.0f / (1.0f + expf(-x)); }

__global__ void lstm_kernel(const float* __restrict__ gates,
                            const float* __restrict__ cprev,
                            bf16* __restrict__ hh, bf16* __restrict__ hl,
                            float* __restrict__ c, float* __restrict__ hf)
{
    const int idx = blockIdx.x * blockDim.x + threadIdx.x;
    const int n = idx >> 8;
    const int j4 = idx & 255;
    const float4* gp = (const float4*)(gates + (size_t)n * G4);
    const float4 gi = gp[j4];
    const float4 gf = gp[256 + j4];
    const float4 gg = gp[512 + j4];
    const float4 go = gp[768 + j4];
    float4 cp = make_float4(0.f, 0.f, 0.f, 0.f);
    if (cprev) cp = ((const float4*)cprev)[idx];
    float4 cn, hn;
    cn.x = sigm(gf.x) * cp.x + sigm(gi.x) * tanhf(gg.x);  hn.x = sigm(go.x) * tanhf(cn.x);
    cn.y = sigm(gf.y) * cp.y + sigm(gi.y) * tanhf(gg.y);  hn.y = sigm(go.y) * tanhf(cn.y);
    cn.z = sigm(gf.z) * cp.z + sigm(gi.z) * tanhf(gg.z);  hn.z = sigm(go.z) * tanhf(cn.z);
    cn.w = sigm(gf.w) * cp.w + sigm(gi.w) * tanhf(gg.w);  hn.w = sigm(go.w) * tanhf(cn.w);
    ((float4*)c)[idx] = cn;
    unsigned short h0, l0, h1, l1, h2, l2, h3, l3;
    split2(hn.x, h0, l0); split2(hn.y, h1, l1); split2(hn.z, h2, l2); split2(hn.w, h3, l3);
    ((ushort4*)hh)[idx] = make_ushort4(h0, h1, h2, h3);
    ((ushort4*)hl)[idx] = make_ushort4(l0, l1, l2, l3);
    if (hf) ((float4*)hf)[idx] = hn;
}

// ---------------- bias prep (bcat has 5120 entries: [bcomb ; bdc]) ----------------
__global__ void prep_kernel(const float* __restrict__ dWih, const float* __restrict__ bdc,
                            const float* __restrict__ dbih, const float* __restrict__ dbhh,
                            const float* __restrict__ ebih, const float* __restrict__ ebhh,
                            float* __restrict__ bdec0, float* __restrict__ bcat,
                            float* __restrict__ benc)
{
    const int g = blockIdx.x;       // 0..NCAT-1
    const int t = threadIdx.x;      // 128
    if (g >= G4) {
        if (t == 0) bcat[g] = bdc[g - G4];
        return;
    }
    float p = 0.f;
    for (int k = t; k < FF; k += 128) p += dWih[(size_t)g * FF + k] * bdc[k];
    p += __shfl_down_sync(0xffffffffu, p, 16);
    p += __shfl_down_sync(0xffffffffu, p, 8);
    p += __shfl_down_sync(0xffffffffu, p, 4);
    p += __shfl_down_sync(0xffffffffu, p, 2);
    p += __shfl_down_sync(0xffffffffu, p, 1);
    __shared__ float sred[4];
    if ((t & 31) == 0) sred[t >> 5] = p;
    __syncthreads();
    if (t == 0) {
        const float srow = sred[0] + sred[1] + sred[2] + sred[3];
        const float b0 = dbih[g] + dbhh[g];
        bdec0[g] = b0;
        bcat[g] = b0 + srow;
        benc[g] = ebih[g] + ebhh[g];
    }
}

// ---------------- skinny head ----------------
__global__ void encscore_kernel(const float* __restrict__ h, const float* __restrict__ Wec,
                                const float* __restrict__ bec, float* __restrict__ out)
{
    const int warp = threadIdx.x >> 5;
    const int lane = threadIdx.x & 31;
    const int r = blockIdx.x * 8 + warp;
    float acc[CC];
#pragma unroll
    for (int n = 0; n < CC; n++) acc[n] = 0.f;
    const float* hr = h + (size_t)r * FF;
    for (int u = 0; u < FF / 32; u++) {
        const float hv = hr[u * 32 + lane];
#pragma unroll
        for (int n = 0; n < CC; n++) acc[n] += hv * Wec[n * FF + u * 32 + lane];
    }
#pragma unroll
    for (int n = 0; n < CC; n++) {
        float v = acc[n];
        v += __shfl_xor_sync(0xffffffffu, v, 16);
        v += __shfl_xor_sync(0xffffffffu, v, 8);
        v += __shfl_xor_sync(0xffffffffu, v, 4);
        v += __shfl_xor_sync(0xffffffffu, v, 2);
        v += __shfl_xor_sync(0xffffffffu, v, 1);
        if (lane == 0) out[(size_t)r * CC + n] = v + bec[n];
    }
}

// ---------------- launch ----------------
extern "C" void kernel_launch(void* const* d_in, const int* in_sizes, int n_in,
                              void* d_out, int out_size)
{
    const float* x    = (const float*)d_in[0];
    const float* Wf   = (const float*)d_in[1];
    const float* bf   = (const float*)d_in[2];
    const float* dWih = (const float*)d_in[3];
    const float* dWhh = (const float*)d_in[4];
    const float* dbih = (const float*)d_in[5];
    const float* dbhh = (const float*)d_in[6];
    const float* Wdc  = (const float*)d_in[7];
    const float* bdc  = (const float*)d_in[8];
    const float* eWih = (const float*)d_in[9];
    const float* eWhh = (const float*)d_in[10];
    const float* ebih = (const float*)d_in[11];
    const float* ebhh = (const float*)d_in[12];
    const float* Wec  = (const float*)d_in[13];
    const float* bec  = (const float*)d_in[14];

    float* enc_out = (float*)d_out;
    float* dec_out = (float*)d_out + (size_t)NROW * CC;

    unsigned char* ar = nullptr;
    cudaGetSymbolAddress((void**)&ar, g_arena);

    bf16* xh  = (bf16*)(ar + O_XH);   bf16* xl  = (bf16*)(ar + O_XL);
    bf16* Wfh = (bf16*)(ar + O_WFH);  bf16* Wfl = (bf16*)(ar + O_WFL);
    bf16* dih = (bf16*)(ar + O_DIH);  bf16* dil = (bf16*)(ar + O_DIL);
    bf16* eih = (bf16*)(ar + O_EIH);  bf16* eil = (bf16*)(ar + O_EIL);
    bf16* ehh = (bf16*)(ar + O_EHH);  bf16* ehl = (bf16*)(ar + O_EHL);
    bf16* wth = (bf16*)(ar + O_WTH);  bf16* wtl = (bf16*)(ar + O_WTL);
    bf16* wch = (bf16*)(ar + O_WCH);  bf16* wcl = (bf16*)(ar + O_WCL);
    bf16* wdh = wch + (size_t)G4 * HH;   // Wdc split lives in rows 4096..5119
    bf16* wdl = wcl + (size_t)G4 * HH;
    bf16* fh  = (bf16*)(ar + O_FH);   bf16* fl  = (bf16*)(ar + O_FL);
    bf16* hh  = (bf16*)(ar + O_HH);   bf16* hl  = (bf16*)(ar + O_HL);
    bf16* lh  = (bf16*)(ar + O_LH);   bf16* ll  = (bf16*)(ar + O_LL);
    float* cbuf  = (float*)(ar + O_C);
    float* gates = (float*)(ar + O_G);
    float* hfbuf = (float*)(ar + O_HF);
    float* bdec0 = (float*)(ar + O_B0);
    float* bcat  = (float*)(ar + O_B1);
    float* benc  = (float*)(ar + O_B2);

    cudaFuncSetAttribute(tcgemm, cudaFuncAttributeMaxDynamicSharedMemorySize, SMEM_DYN);

    // splits
    split_kernel<<<NROW * INN / 1024, 256>>>(x, xh, xl);
    split_kernel<<<FF * INN / 1024, 256>>>(Wf, Wfh, Wfl);
    split_kernel<<<G4 * FF / 1024, 256>>>(dWih, dih, dil);
    split_kernel<<<G4 * FF / 1024, 256>>>(eWih, eih, eil);
    split_kernel<<<G4 * FF / 1024, 256>>>(eWhh, ehh, ehl);
    split_kernel<<<FF * HH / 1024, 256>>>(Wdc, wdh, wdl);
    tsplit_kernel<<<dim3(HH / 32, FF / 32), dim3(32, 32)>>>(Wdc, wth, wtl);
    prep_kernel<<<NCAT, 128>>>(dWih, bdc, dbih, dbhh, ebih, ebhh, bdec0, bcat, benc);

    const dim3 gBig(G4 / 128, NROW / 256);    // 32 x 16
    const dim3 gOut(FF / 128, NROW / 256);    // 8 x 16
    const dim3 gFuse(NCAT / 128, NROW / 256); // 40 x 16
    const dim3 gWc(FF / 128, G4 / 256);       // 8 x 16
    const int  lstmGrid = NROW * HH / 4 / 256;

    Passes P;

    // 1) feats = relu(x @ Wf^T + bf) -> split bf16 only
    P.A[0] = xh; P.B[0] = Wfh;  P.A[1] = xl; P.B[1] = Wfh;  P.A[2] = xh; P.B[2] = Wfl;
    tcgemm<<<gOut, 256, SMEM_DYN>>>(P, 3, INN, FF, bf, nullptr, 0,
                                    nullptr, 0, nullptr, 0, fh, fl, FF, 1.0f, 1);

    // 2) Wcomb = dWih @ Wdc + dWhh  (B = WdcT split) -> split bf16 rows 0..4095 of wch/wcl
    P.A[0] = dih; P.B[0] = wth;  P.A[1] = dil; P.B[1] = wth;  P.A[2] = dih; P.B[2] = wtl;
    tcgemm<<<gWc, 256, SMEM_DYN>>>(P, 3, FF, FF, nullptr, dWhh, HH,
                                   nullptr, 0, nullptr, 0, wch, wcl, HH, 1.0f, 0);

    // 3) decoder step 0: gates = feats @ dWih^T + bdec0
    P.A[0] = fh; P.B[0] = dih;  P.A[1] = fl; P.B[1] = dih;  P.A[2] = fh; P.B[2] = dil;
    tcgemm<<<gBig, 256, SMEM_DYN>>>(P, 3, FF, G4, bdec0, nullptr, 0,
                                    gates, G4, nullptr, 0, nullptr, nullptr, 0, 1.0f, 0);
    lstm_kernel<<<lstmGrid, 256>>>(gates, nullptr, hh, hl, cbuf, nullptr);

    // 4) fused decoder steps: [gates_{t+1} | out_t] = h_t @ [Wcomb | Wdc]^T + bcat
    for (int t = 0; t < DD - 1; t++) {
        P.A[0] = hh; P.B[0] = wch;  P.A[1] = hl; P.B[1] = wch;  P.A[2] = hh; P.B[2] = wcl;
        tcgemm<<<gFuse, 256, SMEM_DYN>>>(P, 3, HH, G4, bcat, nullptr, 0,
                                         gates, G4, dec_out + (size_t)t * FF, DD * FF,
                                         nullptr, nullptr, 0, 1.0f, 0);
        lstm_kernel<<<lstmGrid, 256>>>(gates, cbuf, hh, hl, cbuf, nullptr);
    }

    // 5) out_7 = h_7 @ Wdc^T + bdc ; also emits split(v/D) for encoder h0
    P.A[0] = hh; P.B[0] = wdh;  P.A[1] = hl; P.B[1] = wdh;  P.A[2] = hh; P.B[2] = wdl;
    tcgemm<<<gOut, 256, SMEM_DYN>>>(P, 3, HH, FF, bdc, nullptr, 0,
                                    dec_out + (size_t)(DD - 1) * FF, DD * FF,
                                    nullptr, 0, lh, ll, FF, 1.0f / (float)DD, 0);

    // 6) encoder gates = feats @ eWih^T + (last/D) @ eWhh^T + benc  (6 passes)
    P.A[0] = fh; P.B[0] = eih;  P.A[1] = fl; P.B[1] = eih;  P.A[2] = fh; P.B[2] = eil;
    P.A[3] = lh; P.B[3] = ehh;  P.A[4] = ll; P.B[4] = ehh;  P.A[5] = lh; P.B[5] = ehl;
    tcgemm<<<gBig, 256, SMEM_DYN>>>(P, 6, FF, G4, benc, nullptr, 0,
                                    gates, G4, nullptr, 0, nullptr, nullptr, 0, 1.0f, 0);
    lstm_kernel<<<lstmGrid, 256>>>(gates, nullptr, hh, hl, cbuf, hfbuf);

    encscore_kernel<<<NROW / 8, 256>>>(hfbuf, Wec, bec, enc_out);
}

// round 9
// speedup vs baseline: 1.3437x; 1.3437x over previous
#include <cuda_runtime.h>
#include <cuda_bf16.h>
#include <math.h>
#include <stdint.h>

#define DD   8
#define FF   1024
#define HH   1024
#define CC   22
#define INN  4096
#define NROW 4096
#define G4   4096
#define NCAT (G4 + FF)    // 5120

typedef __nv_bfloat16 bf16;

// ---------------- arena ----------------
constexpr size_t SZ_X  = (size_t)NROW * INN * 2;
constexpr size_t SZ_W4 = (size_t)G4 * FF * 2;
constexpr size_t SZ_W1 = (size_t)FF * HH * 2;
constexpr size_t SZ_WC = (size_t)NCAT * HH * 2;

constexpr size_t O_XH  = 0;
constexpr size_t O_XL  = O_XH + SZ_X;
constexpr size_t O_WFH = O_XL + SZ_X;
constexpr size_t O_WFL = O_WFH + SZ_W4;
constexpr size_t O_DIH = O_WFL + SZ_W4;
constexpr size_t O_DIL = O_DIH + SZ_W4;
constexpr size_t O_EIH = O_DIL + SZ_W4;
constexpr size_t O_EIL = O_EIH + SZ_W4;
constexpr size_t O_EHH = O_EIL + SZ_W4;
constexpr size_t O_EHL = O_EHH + SZ_W4;
constexpr size_t O_WTH = O_EHL + SZ_W4;
constexpr size_t O_WTL = O_WTH + SZ_W1;
constexpr size_t O_WCH = O_WTL + SZ_W1;      // [NCAT, HH]: rows 0..4095 Wcomb, 4096.. Wdc
constexpr size_t O_WCL = O_WCH + SZ_WC;
constexpr size_t O_FH  = O_WCL + SZ_WC;
constexpr size_t O_FL  = O_FH + SZ_W4;
constexpr size_t O_HH  = O_FL + SZ_W4;
constexpr size_t O_HL  = O_HH + SZ_W4;
constexpr size_t O_LH  = O_HL + SZ_W4;
constexpr size_t O_LL  = O_LH + SZ_W4;
constexpr size_t O_C   = O_LL + SZ_W4;
constexpr size_t O_G   = O_C  + (size_t)NROW * HH * 4;
constexpr size_t O_HF  = O_G  + (size_t)NROW * G4 * 4;
constexpr size_t O_B0  = O_HF + (size_t)NROW * HH * 4;
constexpr size_t O_B1  = O_B0 + (size_t)G4 * 4;     // bcat: 5120 floats
constexpr size_t O_B2  = O_B1 + (size_t)NCAT * 4;
constexpr size_t ARENA = O_B2 + (size_t)G4 * 4;

__device__ __align__(1024) unsigned char g_arena[ARENA];

// ---------------- helpers ----------------
__device__ __forceinline__ uint32_t smem_u32(const void* p) {
    uint32_t a;
    asm("{ .reg .u64 t; cvta.to.shared.u64 t, %1; cvt.u32.u64 %0, t; }" : "=r"(a) : "l"(p));
    return a;
}
__device__ __forceinline__ void ldsm4(uint32_t& r0, uint32_t& r1, uint32_t& r2, uint32_t& r3,
                                      uint32_t addr) {
    asm volatile("ldmatrix.sync.aligned.m8n8.x4.shared.b16 {%0,%1,%2,%3}, [%4];"
                 : "=r"(r0), "=r"(r1), "=r"(r2), "=r"(r3) : "r"(addr));
}
__device__ __forceinline__ void mma16816(float* c, const uint32_t* a, const uint32_t* b) {
    asm volatile("mma.sync.aligned.m16n8k16.row.col.f32.bf16.bf16.f32 "
                 "{%0,%1,%2,%3}, {%4,%5,%6,%7}, {%8,%9}, {%0,%1,%2,%3};"
                 : "+f"(c[0]), "+f"(c[1]), "+f"(c[2]), "+f"(c[3])
                 : "r"(a[0]), "r"(a[1]), "r"(a[2]), "r"(a[3]), "r"(b[0]), "r"(b[1]));
}
__device__ __forceinline__ void split2(float v, unsigned short& hi, unsigned short& lo) {
    bf16 h = __float2bfloat16(v);
    bf16 l = __float2bfloat16(v - __bfloat162float(h));
    hi = *(unsigned short*)&h;
    lo = *(unsigned short*)&l;
}

// ---------------- HMMA split-bf16 GEMM (CTA 128x128, warp 64x32, 2 CTA/SM) ----------------
// C[M,N] = sum_p A_p @ B_p^T ; A_p [M,Kp], B_p [N,Kp] row-major bf16 (K-major).
// Epilogue: cols < N1 -> C1 (+bias, +Cadd, relu, optional split-bf16 out of v*oscale);
//           cols >= N1 -> C2 (+bias only), stored at col-N1.
struct Passes { const bf16* A[6]; const bf16* B[6]; };

#define STAGES      4
#define ROWPITCH    80                  // 64B data + 16B pad (conflict-free ldmatrix)
#define A_BYTES     (128 * ROWPITCH)    // 10240
#define STAGE_BYTES (2 * A_BYTES)       // 20480
#define SMEM_DYN    (STAGES * STAGE_BYTES)

__global__ __launch_bounds__(256, 2)
void tcgemm(Passes P, int nPass, int Kp, int N1,
            const float* __restrict__ bias,
            const float* __restrict__ Cadd, int ldadd,
            float* __restrict__ C1, int ldc1,
            float* __restrict__ C2, int ldc2,
            bf16* __restrict__ Oh, bf16* __restrict__ Ol, int ldo,
            float oscale, int relu)
{
    extern __shared__ __align__(16) unsigned char dsm[];
    const uint32_t sbase = smem_u32(dsm);

    const int tid = threadIdx.x, wid = tid >> 5, lane = tid & 31;
    const int wm = wid >> 2;        // 0..1  (64-row halves)
    const int wn = wid & 3;         // 0..3  (32-col quarters)
    const int tm = blockIdx.y, tn = blockIdx.x;

    const int ck  = Kp >> 5;
    const int nkt = nPass * ck;

    auto load_chunk = [&](int f) {
        const int buf = f & 3;
        const int p = f / ck, ko = (f - p * ck) << 5;
        const bf16* Ag = P.A[p] + (size_t)(tm * 128) * Kp + ko;
        const bf16* Bg = P.B[p] + (size_t)(tn * 128) * Kp + ko;
        const uint32_t sA = sbase + (uint32_t)buf * STAGE_BYTES;
        const uint32_t sB = sA + A_BYTES;
#pragma unroll
        for (int j = 0; j < 2; j++) {
            const int i = tid + 256 * j;
            const int row = i >> 2, ch = i & 3;
            const uint32_t d = (uint32_t)row * ROWPITCH + (uint32_t)ch * 16;
            asm volatile("cp.async.cg.shared.global [%0], [%1], 16;"
                         :: "r"(sA + d), "l"(Ag + (size_t)row * Kp + ch * 8) : "memory");
            asm volatile("cp.async.cg.shared.global [%0], [%1], 16;"
                         :: "r"(sB + d), "l"(Bg + (size_t)row * Kp + ch * 8) : "memory");
        }
        asm volatile("cp.async.commit_group;" ::: "memory");
    };

    float c[4][4][4];
#pragma unroll
    for (int i = 0; i < 4; i++)
#pragma unroll
        for (int j = 0; j < 4; j++)
#pragma unroll
            for (int k = 0; k < 4; k++) c[i][j][k] = 0.f;

    const uint32_t a_row = (uint32_t)(wm * 64 + (lane & 15));
    const uint32_t a_ch  = (uint32_t)((lane >> 4) * 16);
    const uint32_t b_row = (uint32_t)(wn * 32 + ((lane >> 4) << 3) + (lane & 7));
    const uint32_t b_ch  = (uint32_t)(((lane >> 3) & 1) * 16);

    for (int f = 0; f < STAGES - 1 && f < nkt; f++) load_chunk(f);

    for (int kt = 0; kt < nkt; kt++) {
        int w = nkt - kt - 1;
        if (w > STAGES - 2) w = STAGES - 2;
        if (w == 2)      asm volatile("cp.async.wait_group 2;" ::: "memory");
        else if (w == 1) asm volatile("cp.async.wait_group 1;" ::: "memory");
        else             asm volatile("cp.async.wait_group 0;" ::: "memory");
        __syncthreads();

        const int f = kt + STAGES - 1;
        if (f < nkt) load_chunk(f);

        const uint32_t sA = sbase + (uint32_t)(kt & 3) * STAGE_BYTES;
        const uint32_t sB = sA + A_BYTES;
#pragma unroll
        for (int ks = 0; ks < 2; ks++) {
            uint32_t a[4][4], b[4][2];
#pragma unroll
            for (int mf = 0; mf < 4; mf++) {
                const uint32_t addr = sA + (a_row + mf * 16) * ROWPITCH + ks * 32 + a_ch;
                ldsm4(a[mf][0], a[mf][1], a[mf][2], a[mf][3], addr);
            }
#pragma unroll
            for (int np = 0; np < 2; np++) {
                const uint32_t addr = sB + (b_row + np * 16) * ROWPITCH + ks * 32 + b_ch;
                ldsm4(b[2 * np][0], b[2 * np][1], b[2 * np + 1][0], b[2 * np + 1][1], addr);
            }
#pragma unroll
            for (int mf = 0; mf < 4; mf++)
#pragma unroll
                for (int nf = 0; nf < 4; nf++)
                    mma16816(c[mf][nf], a[mf], b[nf]);
        }
    }

    // ---------------- epilogue ----------------
    const int tr = lane >> 2, tc = (lane & 3) * 2;
#pragma unroll
    for (int mf = 0; mf < 4; mf++) {
#pragma unroll
        for (int half = 0; half < 2; half++) {
            const size_t row = (size_t)tm * 128 + wm * 64 + mf * 16 + tr + half * 8;
            float* c1row = C1 ? C1 + row * (size_t)ldc1 : (float*)0;
            float* c2row = C2 ? C2 + row * (size_t)ldc2 : (float*)0;
            const float* arow = Cadd ? Cadd + row * (size_t)ldadd : (const float*)0;
            bf16* ohr = Oh ? Oh + row * (size_t)ldo : (bf16*)0;
            bf16* olr = Ol ? Ol + row * (size_t)ldo : (bf16*)0;
#pragma unroll
            for (int nf = 0; nf < 4; nf++) {
                const int col = tn * 128 + wn * 32 + nf * 8 + tc;
                float vx = c[mf][nf][half * 2 + 0];
                float vy = c[mf][nf][half * 2 + 1];
                if (bias) { vx += bias[col]; vy += bias[col + 1]; }
                if (col < N1) {
                    if (arow) { vx += arow[col]; vy += arow[col + 1]; }
                    if (relu) { vx = fmaxf(vx, 0.f); vy = fmaxf(vy, 0.f); }
                    if (c1row) *(float2*)(c1row + col) = make_float2(vx, vy);
                    if (ohr) {
                        unsigned short h0, l0, h1, l1;
                        split2(vx * oscale, h0, l0);
                        split2(vy * oscale, h1, l1);
                        *(ushort2*)((unsigned short*)ohr + col) = make_ushort2(h0, h1);
                        *(ushort2*)((unsigned short*)olr + col) = make_ushort2(l0, l1);
                    }
                } else {
                    *(float2*)(c2row + (col - N1)) = make_float2(vx, vy);
                }
            }
        }
    }
}

// ---------------- split fp32 -> (bf16 hi, bf16 lo) ----------------
__global__ void split_kernel(const float* __restrict__ s,
                             bf16* __restrict__ h, bf16* __restrict__ l)
{
    const size_t i = (size_t)blockIdx.x * 256 + threadIdx.x;
    const float4 v = ((const float4*)s)[i];
    unsigned short h0, l0, h1, l1, h2, l2, h3, l3;
    split2(v.x, h0, l0); split2(v.y, h1, l1); split2(v.z, h2, l2); split2(v.w, h3, l3);
    ((ushort4*)h)[i] = make_ushort4(h0, h1, h2, h3);
    ((ushort4*)l)[i] = make_ushort4(l0, l1, l2, l3);
}

// transpose + split: WdcT[h,f] = Wdc[f,h]
__global__ void tsplit_kernel(const float* __restrict__ W,
                              bf16* __restrict__ th, bf16* __restrict__ tl)
{
    __shared__ float t[32][33];
    const int f0 = blockIdx.y * 32, h0 = blockIdx.x * 32;
    t[threadIdx.y][threadIdx.x] = W[(size_t)(f0 + threadIdx.y) * HH + h0 + threadIdx.x];
    __syncthreads();
    const float v = t[threadIdx.x][threadIdx.y];
    unsigned short hi, lo;
    split2(v, hi, lo);
    const size_t o = (size_t)(h0 + threadIdx.y) * FF + f0 + threadIdx.x;
    ((unsigned short*)th)[o] = hi;
    ((unsigned short*)tl)[o] = lo;
}

// ---------------- LSTM pointwise ----------------
__device__ __forceinline__ float sigm(float x) { return 1.0f / (1.0f + expf(-x)); }

__global__ void lstm_kernel(const float* __restrict__ gates,
                            const float* __restrict__ cprev,
                            bf16* __restrict__ hh, bf16* __restrict__ hl,
                            float* __restrict__ c, float* __restrict__ hf)
{
    const int idx = blockIdx.x * blockDim.x + threadIdx.x;
    const int n = idx >> 8;
    const int j4 = idx & 255;
    const float4* gp = (const float4*)(gates + (size_t)n * G4);
    const float4 gi = gp[j4];
    const float4 gf = gp[256 + j4];
    const float4 gg = gp[512 + j4];
    const float4 go = gp[768 + j4];
    float4 cp = make_float4(0.f, 0.f, 0.f, 0.f);
    if (cprev) cp = ((const float4*)cprev)[idx];
    float4 cn, hn;
    cn.x = sigm(gf.x) * cp.x + sigm(gi.x) * tanhf(gg.x);  hn.x = sigm(go.x) * tanhf(cn.x);
    cn.y = sigm(gf.y) * cp.y + sigm(gi.y) * tanhf(gg.y);  hn.y = sigm(go.y) * tanhf(cn.y);
    cn.z = sigm(gf.z) * cp.z + sigm(gi.z) * tanhf(gg.z);  hn.z = sigm(go.z) * tanhf(cn.z);
    cn.w = sigm(gf.w) * cp.w + sigm(gi.w) * tanhf(gg.w);  hn.w = sigm(go.w) * tanhf(cn.w);
    ((float4*)c)[idx] = cn;
    unsigned short h0, l0, h1, l1, h2, l2, h3, l3;
    split2(hn.x, h0, l0); split2(hn.y, h1, l1); split2(hn.z, h2, l2); split2(hn.w, h3, l3);
    ((ushort4*)hh)[idx] = make_ushort4(h0, h1, h2, h3);
    ((ushort4*)hl)[idx] = make_ushort4(l0, l1, l2, l3);
    if (hf) ((float4*)hf)[idx] = hn;
}

// ---------------- bias prep (bcat: [bcomb ; bdc], 5120 entries) ----------------
__global__ void prep_kernel(const float* __restrict__ dWih, const float* __restrict__ bdc,
                            const float* __restrict__ dbih, const float* __restrict__ dbhh,
                            const float* __restrict__ ebih, const float* __restrict__ ebhh,
                            float* __restrict__ bdec0, float* __restrict__ bcat,
                            float* __restrict__ benc)
{
    const int g = blockIdx.x;       // 0..NCAT-1
    const int t = threadIdx.x;      // 128
    if (g >= G4) {
        if (t == 0) bcat[g] = bdc[g - G4];
        return;
    }
    float p = 0.f;
    for (int k = t; k < FF; k += 128) p += dWih[(size_t)g * FF + k] * bdc[k];
    p += __shfl_down_sync(0xffffffffu, p, 16);
    p += __shfl_down_sync(0xffffffffu, p, 8);
    p += __shfl_down_sync(0xffffffffu, p, 4);
    p += __shfl_down_sync(0xffffffffu, p, 2);
    p += __shfl_down_sync(0xffffffffu, p, 1);
    __shared__ float sred[4];
    if ((t & 31) == 0) sred[t >> 5] = p;
    __syncthreads();
    if (t == 0) {
        const float srow = sred[0] + sred[1] + sred[2] + sred[3];
        const float b0 = dbih[g] + dbhh[g];
        bdec0[g] = b0;
        bcat[g] = b0 + srow;
        benc[g] = ebih[g] + ebhh[g];
    }
}

// ---------------- skinny head ----------------
__global__ void encscore_kernel(const float* __restrict__ h, const float* __restrict__ Wec,
                                const float* __restrict__ bec, float* __restrict__ out)
{
    const int warp = threadIdx.x >> 5;
    const int lane = threadIdx.x & 31;
    const int r = blockIdx.x * 8 + warp;
    float acc[CC];
#pragma unroll
    for (int n = 0; n < CC; n++) acc[n] = 0.f;
    const float* hr = h + (size_t)r * FF;
    for (int u = 0; u < FF / 32; u++) {
        const float hv = hr[u * 32 + lane];
#pragma unroll
        for (int n = 0; n < CC; n++) acc[n] += hv * Wec[n * FF + u * 32 + lane];
    }
#pragma unroll
    for (int n = 0; n < CC; n++) {
        float v = acc[n];
        v += __shfl_xor_sync(0xffffffffu, v, 16);
        v += __shfl_xor_sync(0xffffffffu, v, 8);
        v += __shfl_xor_sync(0xffffffffu, v, 4);
        v += __shfl_xor_sync(0xffffffffu, v, 2);
        v += __shfl_xor_sync(0xffffffffu, v, 1);
        if (lane == 0) out[(size_t)r * CC + n] = v + bec[n];
    }
}

// ---------------- launch ----------------
extern "C" void kernel_launch(void* const* d_in, const int* in_sizes, int n_in,
                              void* d_out, int out_size)
{
    const float* x    = (const float*)d_in[0];
    const float* Wf   = (const float*)d_in[1];
    const float* bf   = (const float*)d_in[2];
    const float* dWih = (const float*)d_in[3];
    const float* dWhh = (const float*)d_in[4];
    const float* dbih = (const float*)d_in[5];
    const float* dbhh = (const float*)d_in[6];
    const float* Wdc  = (const float*)d_in[7];
    const float* bdc  = (const float*)d_in[8];
    const float* eWih = (const float*)d_in[9];
    const float* eWhh = (const float*)d_in[10];
    const float* ebih = (const float*)d_in[11];
    const float* ebhh = (const float*)d_in[12];
    const float* Wec  = (const float*)d_in[13];
    const float* bec  = (const float*)d_in[14];

    float* enc_out = (float*)d_out;
    float* dec_out = (float*)d_out + (size_t)NROW * CC;

    unsigned char* ar = nullptr;
    cudaGetSymbolAddress((void**)&ar, g_arena);

    bf16* xh  = (bf16*)(ar + O_XH);   bf16* xl  = (bf16*)(ar + O_XL);
    bf16* Wfh = (bf16*)(ar + O_WFH);  bf16* Wfl = (bf16*)(ar + O_WFL);
    bf16* dih = (bf16*)(ar + O_DIH);  bf16* dil = (bf16*)(ar + O_DIL);
    bf16* eih = (bf16*)(ar + O_EIH);  bf16* eil = (bf16*)(ar + O_EIL);
    bf16* ehh = (bf16*)(ar + O_EHH);  bf16* ehl = (bf16*)(ar + O_EHL);
    bf16* wth = (bf16*)(ar + O_WTH);  bf16* wtl = (bf16*)(ar + O_WTL);
    bf16* wch = (bf16*)(ar + O_WCH);  bf16* wcl = (bf16*)(ar + O_WCL);
    bf16* wdh = wch + (size_t)G4 * HH;   // Wdc split = rows 4096..5119 of [Wcomb;Wdc]
    bf16* wdl = wcl + (size_t)G4 * HH;
    bf16* fh  = (bf16*)(ar + O_FH);   bf16* fl  = (bf16*)(ar + O_FL);
    bf16* hh  = (bf16*)(ar + O_HH);   bf16* hl  = (bf16*)(ar + O_HL);
    bf16* lh  = (bf16*)(ar + O_LH);   bf16* ll  = (bf16*)(ar + O_LL);
    float* cbuf  = (float*)(ar + O_C);
    float* gates = (float*)(ar + O_G);
    float* hfbuf = (float*)(ar + O_HF);
    float* bdec0 = (float*)(ar + O_B0);
    float* bcat  = (float*)(ar + O_B1);
    float* benc  = (float*)(ar + O_B2);

    cudaFuncSetAttribute(tcgemm, cudaFuncAttributeMaxDynamicSharedMemorySize, SMEM_DYN);

    // splits
    split_kernel<<<NROW * INN / 1024, 256>>>(x, xh, xl);
    split_kernel<<<FF * INN / 1024, 256>>>(Wf, Wfh, Wfl);
    split_kernel<<<G4 * FF / 1024, 256>>>(dWih, dih, dil);
    split_kernel<<<G4 * FF / 1024, 256>>>(eWih, eih, eil);
    split_kernel<<<G4 * FF / 1024, 256>>>(eWhh, ehh, ehl);
    split_kernel<<<FF * HH / 1024, 256>>>(Wdc, wdh, wdl);
    tsplit_kernel<<<dim3(HH / 32, FF / 32), dim3(32, 32)>>>(Wdc, wth, wtl);
    prep_kernel<<<NCAT, 128>>>(dWih, bdc, dbih, dbhh, ebih, ebhh, bdec0, bcat, benc);

    const dim3 gBig(G4 / 128, NROW / 128);    // 32 x 32
    const dim3 gOut(FF / 128, NROW / 128);    // 8 x 32
    const dim3 gFuse(NCAT / 128, NROW / 128); // 40 x 32
    const dim3 gWc(FF / 128, G4 / 128);       // 8 x 32
    const int  lstmGrid = NROW * HH / 4 / 256;

    Passes P;

    // 1) feats = relu(x @ Wf^T + bf) -> split bf16 only
    P.A[0] = xh; P.B[0] = Wfh;  P.A[1] = xl; P.B[1] = Wfh;  P.A[2] = xh; P.B[2] = Wfl;
    tcgemm<<<gOut, 256, SMEM_DYN>>>(P, 3, INN, FF, bf, nullptr, 0,
                                    nullptr, 0, nullptr, 0, fh, fl, FF, 1.0f, 1);

    // 2) Wcomb = dWih @ Wdc + dWhh  (B = WdcT split) -> split bf16 rows 0..4095 of wch/wcl
    P.A[0] = dih; P.B[0] = wth;  P.A[1] = dil; P.B[1] = wth;  P.A[2] = dih; P.B[2] = wtl;
    tcgemm<<<gWc, 256, SMEM_DYN>>>(P, 3, FF, FF, nullptr, dWhh, HH,
                                   nullptr, 0, nullptr, 0, wch, wcl, HH, 1.0f, 0);

    // 3) decoder step 0: gates = feats @ dWih^T + bdec0
    P.A[0] = fh; P.B[0] = dih;  P.A[1] = fl; P.B[1] = dih;  P.A[2] = fh; P.B[2] = dil;
    tcgemm<<<gBig, 256, SMEM_DYN>>>(P, 3, FF, G4, bdec0, nullptr, 0,
                                    gates, G4, nullptr, 0, nullptr, nullptr, 0, 1.0f, 0);
    lstm_kernel<<<lstmGrid, 256>>>(gates, nullptr, hh, hl, cbuf, nullptr);

    // 4) fused decoder steps: [gates_{t+1} | out_t] = h_t @ [Wcomb ; Wdc]^T + bcat
    for (int t = 0; t < DD - 1; t++) {
        P.A[0] = hh; P.B[0] = wch;  P.A[1] = hl; P.B[1] = wch;  P.A[2] = hh; P.B[2] = wcl;
        tcgemm<<<gFuse, 256, SMEM_DYN>>>(P, 3, HH, G4, bcat, nullptr, 0,
                                         gates, G4, dec_out + (size_t)t * FF, DD * FF,
                                         nullptr, nullptr, 0, 1.0f, 0);
        lstm_kernel<<<lstmGrid, 256>>>(gates, cbuf, hh, hl, cbuf, nullptr);
    }

    // 5) out_7 = h_7 @ Wdc^T + bdc ; also emits split(v/D) for encoder h0
    P.A[0] = hh; P.B[0] = wdh;  P.A[1] = hl; P.B[1] = wdh;  P.A[2] = hh; P.B[2] = wdl;
    tcgemm<<<gOut, 256, SMEM_DYN>>>(P, 3, HH, FF, bdc, nullptr, 0,
                                    dec_out + (size_t)(DD - 1) * FF, DD * FF,
                                    nullptr, 0, lh, ll, FF, 1.0f / (float)DD, 0);

    // 6) encoder gates = feats @ eWih^T + (last/D) @ eWhh^T + benc  (6 passes)
    P.A[0] = fh; P.B[0] = eih;  P.A[1] = fl; P.B[1] = eih;  P.A[2] = fh; P.B[2] = eil;
    P.A[3] = lh; P.B[3] = ehh;  P.A[4] = ll; P.B[4] = ehh;  P.A[5] = lh; P.B[5] = ehl;
    tcgemm<<<gBig, 256, SMEM_DYN>>>(P, 6, FF, G4, benc, nullptr, 0,
                                    gates, G4, nullptr, 0, nullptr, nullptr, 0, 1.0f, 0);
    lstm_kernel<<<lstmGrid, 256>>>(gates, nullptr, hh, hl, cbuf, hfbuf);

    encscore_kernel<<<NROW / 8, 256>>>(hfbuf, Wec, bec, enc_out);
}